// round 14
// baseline (speedup 1.0000x reference)
#include <cuda_runtime.h>
#include <cuda_bf16.h>
#include <math.h>
#include <stdint.h>

#define Bb 8
#define Nn 128
#define Tt 64
#define Dd 512
#define Hh 8
#define HD 64
#define TOPK 16
#define SCALE 0.125f

#define OUT0_ELEMS (Bb*Nn*Tt*Dd)
#define MEAN_ELEMS (Bb*Nn*Nn)
#define ROWS_H     32768          // rows per half

typedef __nv_bfloat16 bf16;

// ---------------- static device scratch ----------------
__device__ float g_z[Bb*Nn*Dd];
__device__ float g_attn[Bb*Hh*Nn*Nn];
__device__ float g_raw[Bb*Hh*Nn*Nn];
__device__ int   g_idx[Bb*Hh*Nn*TOPK];
__device__ bf16  g_hvb[Bb*Nn*Tt*Dd];
__device__ bf16  g_vwb[Dd*Dd];
__device__ bf16  g_owb[Dd*Dd];
__device__ bf16  g_v[Bb*Nn*Tt*Dd];
__device__ bf16  g_mixed[Bb*Nn*Tt*Dd];

// ---------------- fp32 -> bf16 ----------------
__global__ void f2bf(const float4* __restrict__ x, uint2* __restrict__ y, int n4) {
    int i = blockIdx.x * 256 + threadIdx.x;
    if (i >= n4) return;
    float4 f = x[i];
    __nv_bfloat162 a = __floats2bfloat162_rn(f.x, f.y);
    __nv_bfloat162 b = __floats2bfloat162_rn(f.z, f.w);
    uint2 u; u.x = *(unsigned*)&a; u.y = *(unsigned*)&b;
    y[i] = u;
}

// ---------------- z_map mean ----------------
__global__ void zmap_kernel(const float* __restrict__ hmap) {
    int bn = blockIdx.x;
    int d  = threadIdx.x;
    const float* p = hmap + (size_t)bn * Tt * Dd + d;
    float s = 0.f;
    #pragma unroll 8
    for (int t = 0; t < Tt; t++) s += p[t * Dd];
    g_z[bn * Dd + d] = s * (1.0f / Tt);
}

// ================= fused q/k projection + scores + topk (all fp32) =================
// One block per (h, b). Phase 1: q/k 64-dim head slices via K-chunked register GEMM.
// Phase 2: softmax / top-16 (identical math to previous scores2).
__device__ __forceinline__ unsigned fenc(float v) {
    int b = __float_as_int(v);
    return (b >= 0) ? ((unsigned)b | 0x80000000u) : ~(unsigned)b;
}
__device__ __forceinline__ float wmax(float v) {
    #pragma unroll
    for (int o = 16; o; o >>= 1) v = fmaxf(v, __shfl_xor_sync(0xffffffffu, v, o));
    return v;
}
__device__ __forceinline__ float wsum(float v) {
    #pragma unroll
    for (int o = 16; o; o >>= 1) v += __shfl_xor_sync(0xffffffffu, v, o);
    return v;
}

// smem (floats): phase1  zt[64][132] @0, wqs[64][68] @8448, wks[64][68] @12800  (end 17152)
//                phase2  qs[128][68] @0, ks_t[64][132] @8704                    (end 17152)
#define SF_SMEM_FLOATS 17152
#define SF_SMEM_BYTES  (SF_SMEM_FLOATS * 4)

__global__ void __launch_bounds__(256)
scores_fused(const float* __restrict__ adj,
             const float* __restrict__ qw, const float* __restrict__ kw) {
    extern __shared__ float sm[];
    float* zt  = sm;            // [64 k][132]
    float* wqs = sm + 8448;     // [64 k][68]
    float* wks = sm + 12800;    // [64 k][68]
    float* qs  = sm;            // [128 i][68]
    float* kst = sm + 8704;     // [64 d][132]

    int h = blockIdx.x, b = blockIdx.y;
    int tid = threadIdx.x, lane = tid & 31, w = tid >> 5;
    int ti = tid & 31, td = tid >> 5;      // ti -> 4 rows, td -> 8 dims

    float accq[4][8], acck[4][8];
    #pragma unroll
    for (int ii = 0; ii < 4; ii++)
        #pragma unroll
        for (int dd = 0; dd < 8; dd++) { accq[ii][dd] = 0.f; acck[ii][dd] = 0.f; }

    // ---- phase 1: q/k projection for this (b, h) ----
    for (int kc = 0; kc < 8; kc++) {
        #pragma unroll
        for (int it = 0; it < 8; it++) {           // z chunk transposed
            int idx = tid + it * 256;              // 0..2047
            int i = idx >> 4, c4 = (idx & 15) * 4;
            float4 v = *(const float4*)(g_z + (size_t)(b * 128 + i) * 512 + kc * 64 + c4);
            zt[(c4 + 0) * 132 + i] = v.x; zt[(c4 + 1) * 132 + i] = v.y;
            zt[(c4 + 2) * 132 + i] = v.z; zt[(c4 + 3) * 132 + i] = v.w;
        }
        #pragma unroll
        for (int it = 0; it < 4; it++) {           // weight chunks transposed
            int idx = tid + it * 256;              // 0..1023
            int d = idx >> 4, c4 = (idx & 15) * 4;
            float4 a = *(const float4*)(qw + (size_t)(h * 64 + d) * 512 + kc * 64 + c4);
            wqs[(c4 + 0) * 68 + d] = a.x; wqs[(c4 + 1) * 68 + d] = a.y;
            wqs[(c4 + 2) * 68 + d] = a.z; wqs[(c4 + 3) * 68 + d] = a.w;
            float4 bb = *(const float4*)(kw + (size_t)(h * 64 + d) * 512 + kc * 64 + c4);
            wks[(c4 + 0) * 68 + d] = bb.x; wks[(c4 + 1) * 68 + d] = bb.y;
            wks[(c4 + 2) * 68 + d] = bb.z; wks[(c4 + 3) * 68 + d] = bb.w;
        }
        __syncthreads();
        #pragma unroll 4
        for (int kk = 0; kk < 64; kk++) {
            float4 zv = *(const float4*)&zt[kk * 132 + ti * 4];
            float4 q0 = *(const float4*)&wqs[kk * 68 + td * 8];
            float4 q1 = *(const float4*)&wqs[kk * 68 + td * 8 + 4];
            float4 k0 = *(const float4*)&wks[kk * 68 + td * 8];
            float4 k1 = *(const float4*)&wks[kk * 68 + td * 8 + 4];
            float zr[4] = {zv.x, zv.y, zv.z, zv.w};
            float qd[8] = {q0.x, q0.y, q0.z, q0.w, q1.x, q1.y, q1.z, q1.w};
            float kd[8] = {k0.x, k0.y, k0.z, k0.w, k1.x, k1.y, k1.z, k1.w};
            #pragma unroll
            for (int ii = 0; ii < 4; ii++)
                #pragma unroll
                for (int dd = 0; dd < 8; dd++) {
                    accq[ii][dd] = fmaf(zr[ii], qd[dd], accq[ii][dd]);
                    acck[ii][dd] = fmaf(zr[ii], kd[dd], acck[ii][dd]);
                }
        }
        __syncthreads();
    }

    // ---- write projections into phase-2 smem layout ----
    #pragma unroll
    for (int ii = 0; ii < 4; ii++)
        #pragma unroll
        for (int dd = 0; dd < 8; dd++) {
            qs[(ti * 4 + ii) * 68 + td * 8 + dd] = accq[ii][dd];
            kst[(td * 8 + dd) * 132 + ti * 4 + ii] = acck[ii][dd];
        }
    __syncthreads();

    // ---- phase 2: scores + softmaxes + top-16 (8 warps x 16 rows) ----
    for (int r = 0; r < 16; r++) {
        int i = w * 16 + r;
        float2 qr = *(const float2*)&qs[i * 68 + lane * 2];
        float a0 = 0.f, a1 = 0.f, a2 = 0.f, a3 = 0.f;
        #pragma unroll
        for (int d = 0; d < 64; d++) {
            float qd = __shfl_sync(0xffffffffu, (d & 1) ? qr.y : qr.x, d >> 1);
            float4 kv = *(const float4*)&kst[d * 132 + lane * 4];
            a0 = fmaf(qd, kv.x, a0); a1 = fmaf(qd, kv.y, a1);
            a2 = fmaf(qd, kv.z, a2); a3 = fmaf(qd, kv.w, a3);
        }
        float4 adjv = *(const float4*)(adj + (size_t)(b * 128 + i) * 128 + lane * 4);
        float s4[4];
        s4[0] = a0 * SCALE + logf(fmaxf(adjv.x, 1e-12f));
        s4[1] = a1 * SCALE + logf(fmaxf(adjv.y, 1e-12f));
        s4[2] = a2 * SCALE + logf(fmaxf(adjv.z, 1e-12f));
        s4[3] = a3 * SCALE + logf(fmaxf(adjv.w, 1e-12f));

        float m = wmax(fmaxf(fmaxf(s4[0], s4[1]), fmaxf(s4[2], s4[3])));
        float e4[4];
        #pragma unroll
        for (int q = 0; q < 4; q++) e4[q] = expf(s4[q] - m);
        float sum1 = wsum(e4[0] + e4[1] + e4[2] + e4[3]);

        size_t rb = ((size_t)(b * 8 + h) * 128 + i) * 128;
        float4 rv; rv.x = e4[0]/sum1; rv.y = e4[1]/sum1; rv.z = e4[2]/sum1; rv.w = e4[3]/sum1;
        *(float4*)(g_raw + rb + lane * 4) = rv;

        unsigned u4[4];
        #pragma unroll
        for (int q = 0; q < 4; q++) u4[q] = fenc(s4[q]);
        int myj = 0;
        for (int itk = 0; itk < TOPK; itk++) {
            unsigned ub = u4[0]; int jb = lane * 4;
            #pragma unroll
            for (int q = 1; q < 4; q++)
                if (u4[q] > ub) { ub = u4[q]; jb = lane * 4 + q; }
            unsigned gm = __reduce_max_sync(0xffffffffu, ub);
            unsigned jm = (ub == gm) ? (unsigned)jb : 0xFFFFu;
            unsigned js = __reduce_min_sync(0xffffffffu, jm);
            if (lane == itk) myj = (int)js;
            if ((js >> 2) == (unsigned)lane) u4[js & 3] = 0u;
        }
        float es = 0.f;
        #pragma unroll
        for (int q = 0; q < 4; q++) if (u4[q] == 0u) es += e4[q];
        float sum2 = wsum(es);
        float4 av;
        av.x = (u4[0] == 0u) ? e4[0]/sum2 : 0.f;
        av.y = (u4[1] == 0u) ? e4[1]/sum2 : 0.f;
        av.z = (u4[2] == 0u) ? e4[2]/sum2 : 0.f;
        av.w = (u4[3] == 0u) ? e4[3]/sum2 : 0.f;
        *(float4*)(g_attn + rb + lane * 4) = av;
        if (lane < TOPK)
            g_idx[((size_t)(b * 8 + h) * 128 + i) * TOPK + lane] = myj;
    }
}

// ================== bf16 HMMA GEMM (R10 champion: BK=32, 4-stage) ==================
__device__ __forceinline__ void cp16(void* smem, const void* g) {
    unsigned s = (unsigned)__cvta_generic_to_shared(smem);
    asm volatile("cp.async.cg.shared.global [%0], [%1], 16;" :: "r"(s), "l"(g));
}
__device__ __forceinline__ void ldsm4(unsigned& r0, unsigned& r1, unsigned& r2, unsigned& r3,
                                      unsigned addr) {
    asm volatile("ldmatrix.sync.aligned.m8n8.x4.shared.b16 {%0,%1,%2,%3}, [%4];"
                 : "=r"(r0), "=r"(r1), "=r"(r2), "=r"(r3) : "r"(addr));
}
__device__ __forceinline__ void mma16816(float* c, const unsigned* a, const unsigned* b) {
    asm volatile(
        "mma.sync.aligned.m16n8k16.row.col.f32.bf16.bf16.f32 "
        "{%0,%1,%2,%3}, {%4,%5,%6,%7}, {%8,%9}, {%0,%1,%2,%3};"
        : "+f"(c[0]), "+f"(c[1]), "+f"(c[2]), "+f"(c[3])
        : "r"(a[0]), "r"(a[1]), "r"(a[2]), "r"(a[3]), "r"(b[0]), "r"(b[1]));
}

#define STAGE_B 20480
#define GSMEM   (4 * STAGE_B)

template <int MODE>
__global__ void __launch_bounds__(128, 2)
mma_gemm4(const bf16* __restrict__ A, const bf16* __restrict__ W, void* __restrict__ Cv,
          const float* __restrict__ hval, const float* __restrict__ rs, int rowBase) {
    extern __shared__ __align__(16) char dynsm[];
    int tid = threadIdx.x;
    int lane = tid & 31, wid = tid >> 5;
    int wm = wid >> 1, wn = wid & 1;
    int brow = rowBase + blockIdx.y * 128, bcol = blockIdx.x * 128;

    const bf16* aptr = A + (size_t)(brow + tid) * 512;
    const bf16* bptr = W + (size_t)(bcol + tid) * 512;
    char* aDst = dynsm + tid * 80;
    char* bDst = dynsm + 10240 + tid * 80;

    unsigned smBase = (unsigned)__cvta_generic_to_shared(dynsm);
    unsigned aOff = (unsigned)((wm * 64 + (lane & 15)) * 80 + ((lane >> 4) << 4));
    unsigned bOff = (unsigned)(10240 + (wn * 64 + ((lane >> 3) & 1) * 8 + (lane & 7)) * 80
                               + ((lane >> 4) << 4));

    float acc[4][8][4];
    #pragma unroll
    for (int i = 0; i < 4; i++)
        #pragma unroll
        for (int j = 0; j < 8; j++)
            #pragma unroll
            for (int e = 0; e < 4; e++) acc[i][j][e] = 0.f;

    #pragma unroll
    for (int s = 0; s < 3; s++) {
        char* ad = aDst + s * STAGE_B;
        char* bd = bDst + s * STAGE_B;
        const bf16* as = aptr + s * 32;
        const bf16* bs = bptr + s * 32;
        #pragma unroll
        for (int c = 0; c < 4; c++) { cp16(ad + c * 16, as + c * 8); cp16(bd + c * 16, bs + c * 8); }
        asm volatile("cp.async.commit_group;");
    }

    #pragma unroll 1
    for (int it = 0; it < 16; it++) {
        if (it < 14)      asm volatile("cp.async.wait_group 2;");
        else if (it == 14) asm volatile("cp.async.wait_group 1;");
        else               asm volatile("cp.async.wait_group 0;");
        __syncthreads();
        if (it + 3 < 16) {
            int s = it + 3;
            char* ad = aDst + (s & 3) * STAGE_B;
            char* bd = bDst + (s & 3) * STAGE_B;
            const bf16* as = aptr + s * 32;
            const bf16* bs = bptr + s * 32;
            #pragma unroll
            for (int c = 0; c < 4; c++) { cp16(ad + c * 16, as + c * 8); cp16(bd + c * 16, bs + c * 8); }
            asm volatile("cp.async.commit_group;");
        }
        unsigned base = smBase + (unsigned)((it & 3) * STAGE_B);
        #pragma unroll
        for (int ks = 0; ks < 2; ks++) {
            unsigned a[4][4], b[8][2];
            #pragma unroll
            for (int mi = 0; mi < 4; mi++)
                ldsm4(a[mi][0], a[mi][1], a[mi][2], a[mi][3],
                      base + aOff + mi * (16 * 80) + ks * 32);
            #pragma unroll
            for (int pr = 0; pr < 4; pr++)
                ldsm4(b[2*pr][0], b[2*pr+1][0], b[2*pr][1], b[2*pr+1][1],
                      base + bOff + pr * (16 * 80) + ks * 32);
            #pragma unroll
            for (int mi = 0; mi < 4; mi++)
                #pragma unroll
                for (int ni = 0; ni < 8; ni++)
                    mma16816(acc[mi][ni], a[mi], b[ni]);
        }
    }

    #pragma unroll
    for (int mi = 0; mi < 4; mi++) {
        int r0 = brow + wm * 64 + mi * 16 + (lane >> 2);
        #pragma unroll
        for (int half = 0; half < 2; half++) {
            int r = r0 + half * 8;
            float sc = 1.f;
            if (MODE == 1) {
                int nseg = (r / Tt) % Nn;
                sc = fminf(fmaxf(rs[nseg], 0.f), 1.f);
            }
            #pragma unroll
            for (int ni = 0; ni < 8; ni++) {
                int c = bcol + wn * 64 + ni * 8 + (lane & 3) * 2;
                float x = acc[mi][ni][half * 2 + 0];
                float y = acc[mi][ni][half * 2 + 1];
                if (MODE == 0) {
                    *(__nv_bfloat162*)((bf16*)Cv + (size_t)r * 512 + c) =
                        __floats2bfloat162_rn(x, y);
                } else {
                    const float2 hv = *(const float2*)(hval + (size_t)r * 512 + c);
                    float2 o; o.x = hv.x + x * sc; o.y = hv.y + y * sc;
                    *(float2*)((float*)Cv + (size_t)r * 512 + c) = o;
                }
            }
        }
    }
}

// ---------------- mixed: smem-tiled sparse mix (+ batch offset) ----------------
__global__ void __launch_bounds__(256)
mixed2(const bf16* __restrict__ v, bf16* __restrict__ mixed, int b0) {
    __shared__ bf16 sv[128][128];
    __shared__ unsigned char su[128][16];
    __shared__ float swt[128][16];
    int nt = blockIdx.x, h = blockIdx.y, b = b0 + blockIdx.z;
    int tid = threadIdx.x, lane = tid & 31, w = tid >> 5;

    {
        int j = tid >> 1, tt = tid & 1;
        const uint4* src = (const uint4*)(v + ((size_t)(b * 128 + j) * 64 + nt * 2 + tt) * 512
                                            + h * 64);
        uint4* dst = (uint4*)&sv[j][tt * 64];
        #pragma unroll
        for (int c = 0; c < 8; c++) dst[c] = src[c];
    }
    {
        int base = (b * 8 + h) * 128;
        #pragma unroll
        for (int e = tid * 8; e < tid * 8 + 8; e++) {
            int i = e >> 4, kk = e & 15;
            int j = g_idx[(size_t)(base + i) * 16 + kk];
            su[i][kk] = (unsigned char)j;
            swt[i][kk] = g_attn[(size_t)(base + i) * 128 + j];
        }
    }
    __syncthreads();

    int tt = lane >> 4;
    for (int r = 0; r < 16; r++) {
        int i = w * 16 + r;
        float a0 = 0.f, a1 = 0.f, a2 = 0.f, a3 = 0.f;
        #pragma unroll
        for (int kk = 0; kk < 16; kk++) {
            int j = su[i][kk];
            float wt = swt[i][kk];
            uint2 vv = *(const uint2*)&sv[j][lane * 4];
            float2 f0 = __bfloat1622float2(*(__nv_bfloat162*)&vv.x);
            float2 f1 = __bfloat1622float2(*(__nv_bfloat162*)&vv.y);
            a0 = fmaf(wt, f0.x, a0); a1 = fmaf(wt, f0.y, a1);
            a2 = fmaf(wt, f1.x, a2); a3 = fmaf(wt, f1.y, a3);
        }
        int d = (lane & 15) * 4;
        __nv_bfloat162 o0 = __floats2bfloat162_rn(a0, a1);
        __nv_bfloat162 o1 = __floats2bfloat162_rn(a2, a3);
        uint2 ov; ov.x = *(unsigned*)&o0; ov.y = *(unsigned*)&o1;
        *(uint2*)(mixed + ((size_t)(b * 128 + i) * 64 + nt * 2 + tt) * 512 + h * 64 + d) = ov;
    }
}

// ---------------- head means ----------------
__global__ void means_kernel(float* __restrict__ out_attn, float* __restrict__ out_raw) {
    int idx = blockIdx.x * 256 + threadIdx.x;
    if (idx >= Bb * Nn * Nn) return;
    int b = idx / (Nn * Nn);
    int rem = idx % (Nn * Nn);
    float sa = 0.f, sr = 0.f;
    #pragma unroll
    for (int h = 0; h < Hh; h++) {
        size_t p = ((size_t)(b * Hh + h)) * Nn * Nn + rem;
        sa += g_attn[p];
        sr += g_raw[p];
    }
    out_attn[idx] = sa * (1.0f / Hh);
    out_raw[idx]  = sr * (1.0f / Hh);
}

// ---------------- launch: R10 two-half pipeline + fused fp32 scores ----------------
extern "C" void kernel_launch(void* const* d_in, const int* in_sizes, int n_in,
                              void* d_out, int out_size) {
    const float* h_val = (const float*)d_in[0];
    const float* h_map = (const float*)d_in[1];
    const float* adj   = (const float*)d_in[2];
    const float* q_w   = (const float*)d_in[3];
    const float* k_w   = (const float*)d_in[4];
    const float* v_w   = (const float*)d_in[5];
    const float* o_w   = (const float*)d_in[6];
    const float* rs    = (const float*)d_in[7];
    float* out = (float*)d_out;

    bf16 *hvb, *vwb, *owb, *v, *mixed;
    cudaGetSymbolAddress((void**)&hvb,   g_hvb);
    cudaGetSymbolAddress((void**)&vwb,   g_vwb);
    cudaGetSymbolAddress((void**)&owb,   g_owb);
    cudaGetSymbolAddress((void**)&v,     g_v);
    cudaGetSymbolAddress((void**)&mixed, g_mixed);

    static cudaStream_t s1 = nullptr, s2 = nullptr;
    static cudaEvent_t evF = nullptr, evW = nullptr, evScores = nullptr,
                       evS1 = nullptr, evB = nullptr;
    if (s1 == nullptr) {
        cudaStreamCreateWithFlags(&s1, cudaStreamNonBlocking);
        cudaStreamCreateWithFlags(&s2, cudaStreamNonBlocking);
        cudaEventCreateWithFlags(&evF,      cudaEventDisableTiming);
        cudaEventCreateWithFlags(&evW,      cudaEventDisableTiming);
        cudaEventCreateWithFlags(&evScores, cudaEventDisableTiming);
        cudaEventCreateWithFlags(&evS1,     cudaEventDisableTiming);
        cudaEventCreateWithFlags(&evB,      cudaEventDisableTiming);
        cudaFuncSetAttribute(mma_gemm4<0>, cudaFuncAttributeMaxDynamicSharedMemorySize, GSMEM);
        cudaFuncSetAttribute(mma_gemm4<1>, cudaFuncAttributeMaxDynamicSharedMemorySize, GSMEM);
        cudaFuncSetAttribute(scores_fused, cudaFuncAttributeMaxDynamicSharedMemorySize,
                             SF_SMEM_BYTES);
    }

    cudaStream_t s0 = 0;
    const int N4H = ROWS_H * Dd / 4;

    // fork
    cudaEventRecord(evF, s0);
    cudaStreamWaitEvent(s1, evF, 0);
    cudaStreamWaitEvent(s2, evF, 0);

    // (1,2) s1: weight converts
    f2bf<<<(Dd*Dd/4 + 255)/256, 256, 0, s1>>>((const float4*)v_w, (uint2*)vwb, Dd*Dd/4);
    f2bf<<<(Dd*Dd/4 + 255)/256, 256, 0, s1>>>((const float4*)o_w, (uint2*)owb, Dd*Dd/4);
    cudaEventRecord(evW, s1);

    // (3,4) s0: half A convert + v-GEMM (index 4 -> profiled)
    f2bf<<<(N4H + 255)/256, 256, 0, s0>>>((const float4*)h_val, (uint2*)hvb, N4H);
    cudaStreamWaitEvent(s0, evW, 0);
    mma_gemm4<0><<<dim3(4, 256), 128, GSMEM, s0>>>(hvb, vwb, (void*)v, nullptr, nullptr, 0);

    // s1: zmap -> fused scores -> means
    zmap_kernel<<<Bb * Nn, Dd, 0, s1>>>(h_map);
    scores_fused<<<dim3(Hh, Bb), 256, SF_SMEM_BYTES, s1>>>(adj, q_w, k_w);
    cudaEventRecord(evScores, s1);
    means_kernel<<<(MEAN_ELEMS + 255)/256, 256, 0, s1>>>(out + OUT0_ELEMS,
                                                         out + OUT0_ELEMS + MEAN_ELEMS);
    cudaEventRecord(evS1, s1);

    // s2: half B convert + v-GEMM
    cudaStreamWaitEvent(s2, evW, 0);
    f2bf<<<(N4H + 255)/256, 256, 0, s2>>>((const float4*)(h_val + (size_t)ROWS_H * Dd),
                                          (uint2*)(hvb + (size_t)ROWS_H * Dd), N4H);
    mma_gemm4<0><<<dim3(4, 256), 128, GSMEM, s2>>>(hvb, vwb, (void*)v, nullptr, nullptr,
                                                   ROWS_H);

    // s0 half A: mixed + o-GEMM
    cudaStreamWaitEvent(s0, evScores, 0);
    mixed2<<<dim3(32, Hh, 4), 256, 0, s0>>>(v, mixed, 0);
    mma_gemm4<1><<<dim3(4, 256), 128, GSMEM, s0>>>(mixed, owb, (void*)out, h_val, rs, 0);

    // s2 half B: mixed + o-GEMM
    cudaStreamWaitEvent(s2, evScores, 0);
    mixed2<<<dim3(32, Hh, 4), 256, 0, s2>>>(v, mixed, 4);
    mma_gemm4<1><<<dim3(4, 256), 128, GSMEM, s2>>>(mixed, owb, (void*)out, h_val, rs,
                                                   ROWS_H);
    cudaEventRecord(evB, s2);

    // final join
    cudaStreamWaitEvent(s0, evB, 0);
    cudaStreamWaitEvent(s0, evS1, 0);
}

// round 15
// speedup vs baseline: 1.0780x; 1.0780x over previous
#include <cuda_runtime.h>
#include <cuda_bf16.h>
#include <math.h>
#include <stdint.h>

#define Bb 8
#define Nn 128
#define Tt 64
#define Dd 512
#define Hh 8
#define HD 64
#define TOPK 16
#define SCALE 0.125f

#define OUT0_ELEMS (Bb*Nn*Tt*Dd)
#define MEAN_ELEMS (Bb*Nn*Nn)
#define ROWS_H     32768          // rows per half

typedef __nv_bfloat16 bf16;

// ---------------- static device scratch ----------------
__device__ float g_z[Bb*Nn*Dd];
__device__ float g_q[Bb*Nn*Dd];
__device__ float g_k[Bb*Nn*Dd];
__device__ float g_wtq[Dd*Dd];
__device__ float g_wtk[Dd*Dd];
__device__ float g_qkp[4*1024*1024];     // K-split partials
__device__ float g_attn[Bb*Hh*Nn*Nn];
__device__ float g_raw[Bb*Hh*Nn*Nn];
__device__ int   g_idx[Bb*Hh*Nn*TOPK];
__device__ bf16  g_hvb[Bb*Nn*Tt*Dd];
__device__ bf16  g_vwb[Dd*Dd];
__device__ bf16  g_owb[Dd*Dd];
__device__ bf16  g_v[Bb*Nn*Tt*Dd];
__device__ bf16  g_mixed[Bb*Nn*Tt*Dd];

// ---------------- fp32 -> bf16 ----------------
__global__ void f2bf(const float4* __restrict__ x, uint2* __restrict__ y, int n4) {
    int i = blockIdx.x * 256 + threadIdx.x;
    if (i >= n4) return;
    float4 f = x[i];
    __nv_bfloat162 a = __floats2bfloat162_rn(f.x, f.y);
    __nv_bfloat162 b = __floats2bfloat162_rn(f.z, f.w);
    uint2 u; u.x = *(unsigned*)&a; u.y = *(unsigned*)&b;
    y[i] = u;
}

// ---------------- weight transpose wt[k][n] = w[n][k] ----------------
__global__ void transpose512(const float* __restrict__ w, float* __restrict__ wt) {
    __shared__ float tile[32][33];
    int bx = blockIdx.x * 32, by = blockIdx.y * 32;
    int tx = threadIdx.x, ty = threadIdx.y;
    #pragma unroll
    for (int i = 0; i < 32; i += 8)
        tile[ty + i][tx] = w[(by + ty + i) * Dd + bx + tx];
    __syncthreads();
    #pragma unroll
    for (int i = 0; i < 32; i += 8)
        wt[(bx + ty + i) * Dd + by + tx] = tile[tx][ty + i];
}

// ---------------- z_map mean ----------------
__global__ void zmap_kernel(const float* __restrict__ hmap) {
    int bn = blockIdx.x;
    int d  = threadIdx.x;
    const float* p = hmap + (size_t)bn * Tt * Dd + d;
    float s = 0.f;
    #pragma unroll 8
    for (int t = 0; t < Tt; t++) s += p[t * Dd];
    g_z[bn * Dd + d] = s * (1.0f / Tt);
}

// ---------------- q/k projection: K-split partials (full wave), fp32 ----------------
__global__ void __launch_bounds__(256)
qk_part(float* __restrict__ part) {
    __shared__ float As[8][128];
    __shared__ float Bs[8][128];
    int bx = blockIdx.x, by = blockIdx.y, kc = blockIdx.z;
    const float* Bt = (bx < 4) ? g_wtq : g_wtk;
    int bcolL = (bx & 3) * 128;
    int brow = by * 128;
    int kbase = kc * 128;
    int tid = threadIdx.x;
    int tr = (tid / 16) * 8, tc = (tid % 16) * 8;
    int aRow = tid >> 1, aCol4 = (tid & 1) * 4;
    int bRow = tid >> 5, bCol4 = (tid & 31) * 4;

    float acc[8][8];
    #pragma unroll
    for (int i = 0; i < 8; i++)
        #pragma unroll
        for (int j = 0; j < 8; j++) acc[i][j] = 0.f;

    for (int k0 = 0; k0 < 128; k0 += 8) {
        float4 av = *(const float4*)(g_z + (size_t)(brow + aRow) * 512 + kbase + k0 + aCol4);
        As[aCol4 + 0][aRow] = av.x; As[aCol4 + 1][aRow] = av.y;
        As[aCol4 + 2][aRow] = av.z; As[aCol4 + 3][aRow] = av.w;
        *(float4*)&Bs[bRow][bCol4] =
            *(const float4*)(Bt + (size_t)(kbase + k0 + bRow) * 512 + bcolL + bCol4);
        __syncthreads();
        #pragma unroll
        for (int kk = 0; kk < 8; kk++) {
            float ar[8], br[8];
            *(float4*)&ar[0] = *(float4*)&As[kk][tr];
            *(float4*)&ar[4] = *(float4*)&As[kk][tr + 4];
            *(float4*)&br[0] = *(float4*)&Bs[kk][tc];
            *(float4*)&br[4] = *(float4*)&Bs[kk][tc + 4];
            #pragma unroll
            for (int i = 0; i < 8; i++)
                #pragma unroll
                for (int j = 0; j < 8; j++) acc[i][j] = fmaf(ar[i], br[j], acc[i][j]);
        }
        __syncthreads();
    }
    #pragma unroll
    for (int i = 0; i < 8; i++) {
        int r = brow + tr + i;
        #pragma unroll
        for (int g = 0; g < 2; g++) {
            int c = bx * 128 + tc + g * 4;
            float4 o;
            o.x = acc[i][g*4+0]; o.y = acc[i][g*4+1];
            o.z = acc[i][g*4+2]; o.w = acc[i][g*4+3];
            *(float4*)(part + ((size_t)kc * 1024 + r) * 1024 + c) = o;
        }
    }
}

__global__ void qk_reduce(const float* __restrict__ part) {
    int i4 = blockIdx.x * 256 + threadIdx.x;
    if (i4 >= 1024 * 256) return;
    int row = i4 >> 8, col = (i4 & 255) * 4;
    float4 s = *(const float4*)(part + (size_t)row * 1024 + col);
    #pragma unroll
    for (int kc = 1; kc < 4; kc++) {
        float4 p = *(const float4*)(part + ((size_t)kc * 1024 + row) * 1024 + col);
        s.x += p.x; s.y += p.y; s.z += p.z; s.w += p.w;
    }
    if (col < 512) *(float4*)(g_q + (size_t)row * 512 + col) = s;
    else           *(float4*)(g_k + (size_t)row * 512 + col - 512) = s;
}

// ---------------- scores (warp-per-row, REDUX topk) ----------------
__device__ __forceinline__ unsigned fenc(float v) {
    int b = __float_as_int(v);
    return (b >= 0) ? ((unsigned)b | 0x80000000u) : ~(unsigned)b;
}
__device__ __forceinline__ float wmax(float v) {
    #pragma unroll
    for (int o = 16; o; o >>= 1) v = fmaxf(v, __shfl_xor_sync(0xffffffffu, v, o));
    return v;
}
__device__ __forceinline__ float wsum(float v) {
    #pragma unroll
    for (int o = 16; o; o >>= 1) v += __shfl_xor_sync(0xffffffffu, v, o);
    return v;
}

__global__ void __launch_bounds__(256)
scores2(const float* __restrict__ adj) {
    __shared__ float ks[64][128];
    int ih = blockIdx.x, h = blockIdx.y, b = blockIdx.z;
    int tid = threadIdx.x, lane = tid & 31, w = tid >> 5;

    {
        int j = tid >> 1, dh = (tid & 1) * 32;
        const float* kp = g_k + (size_t)(b * 128 + j) * 512 + h * 64 + dh;
        #pragma unroll
        for (int f = 0; f < 8; f++) {
            float4 v = *(const float4*)(kp + f * 4);
            ks[dh + f*4 + 0][j] = v.x; ks[dh + f*4 + 1][j] = v.y;
            ks[dh + f*4 + 2][j] = v.z; ks[dh + f*4 + 3][j] = v.w;
        }
    }
    __syncthreads();

    for (int r = 0; r < 8; r++) {
        int i = ih * 64 + w * 8 + r;
        float2 qr = *(const float2*)(g_q + (size_t)(b * 128 + i) * 512 + h * 64 + lane * 2);
        float a0 = 0.f, a1 = 0.f, a2 = 0.f, a3 = 0.f;
        #pragma unroll
        for (int d = 0; d < 64; d++) {
            float qd = __shfl_sync(0xffffffffu, (d & 1) ? qr.y : qr.x, d >> 1);
            float4 kv = *(const float4*)&ks[d][lane * 4];
            a0 = fmaf(qd, kv.x, a0); a1 = fmaf(qd, kv.y, a1);
            a2 = fmaf(qd, kv.z, a2); a3 = fmaf(qd, kv.w, a3);
        }
        float4 adjv = *(const float4*)(adj + (size_t)(b * 128 + i) * 128 + lane * 4);
        float s4[4];
        s4[0] = a0 * SCALE + logf(fmaxf(adjv.x, 1e-12f));
        s4[1] = a1 * SCALE + logf(fmaxf(adjv.y, 1e-12f));
        s4[2] = a2 * SCALE + logf(fmaxf(adjv.z, 1e-12f));
        s4[3] = a3 * SCALE + logf(fmaxf(adjv.w, 1e-12f));

        float m = wmax(fmaxf(fmaxf(s4[0], s4[1]), fmaxf(s4[2], s4[3])));
        float e4[4];
        #pragma unroll
        for (int q = 0; q < 4; q++) e4[q] = expf(s4[q] - m);
        float sum1 = wsum(e4[0] + e4[1] + e4[2] + e4[3]);

        size_t rb = ((size_t)(b * 8 + h) * 128 + i) * 128;
        float4 rv; rv.x = e4[0]/sum1; rv.y = e4[1]/sum1; rv.z = e4[2]/sum1; rv.w = e4[3]/sum1;
        *(float4*)(g_raw + rb + lane * 4) = rv;

        unsigned u4[4];
        #pragma unroll
        for (int q = 0; q < 4; q++) u4[q] = fenc(s4[q]);
        int myj = 0;
        for (int itk = 0; itk < TOPK; itk++) {
            unsigned ub = u4[0]; int jb = lane * 4;
            #pragma unroll
            for (int q = 1; q < 4; q++)
                if (u4[q] > ub) { ub = u4[q]; jb = lane * 4 + q; }
            unsigned gm = __reduce_max_sync(0xffffffffu, ub);
            unsigned jm = (ub == gm) ? (unsigned)jb : 0xFFFFu;
            unsigned js = __reduce_min_sync(0xffffffffu, jm);
            if (lane == itk) myj = (int)js;
            if ((js >> 2) == (unsigned)lane) u4[js & 3] = 0u;
        }
        float es = 0.f;
        #pragma unroll
        for (int q = 0; q < 4; q++) if (u4[q] == 0u) es += e4[q];
        float sum2 = wsum(es);
        float4 av;
        av.x = (u4[0] == 0u) ? e4[0]/sum2 : 0.f;
        av.y = (u4[1] == 0u) ? e4[1]/sum2 : 0.f;
        av.z = (u4[2] == 0u) ? e4[2]/sum2 : 0.f;
        av.w = (u4[3] == 0u) ? e4[3]/sum2 : 0.f;
        *(float4*)(g_attn + rb + lane * 4) = av;
        if (lane < TOPK)
            g_idx[((size_t)(b * 8 + h) * 128 + i) * TOPK + lane] = myj;
    }
}

// ================== bf16 HMMA GEMM (R10 champion: BK=32, 4-stage) ==================
__device__ __forceinline__ void cp16(void* smem, const void* g) {
    unsigned s = (unsigned)__cvta_generic_to_shared(smem);
    asm volatile("cp.async.cg.shared.global [%0], [%1], 16;" :: "r"(s), "l"(g));
}
__device__ __forceinline__ void ldsm4(unsigned& r0, unsigned& r1, unsigned& r2, unsigned& r3,
                                      unsigned addr) {
    asm volatile("ldmatrix.sync.aligned.m8n8.x4.shared.b16 {%0,%1,%2,%3}, [%4];"
                 : "=r"(r0), "=r"(r1), "=r"(r2), "=r"(r3) : "r"(addr));
}
__device__ __forceinline__ void mma16816(float* c, const unsigned* a, const unsigned* b) {
    asm volatile(
        "mma.sync.aligned.m16n8k16.row.col.f32.bf16.bf16.f32 "
        "{%0,%1,%2,%3}, {%4,%5,%6,%7}, {%8,%9}, {%0,%1,%2,%3};"
        : "+f"(c[0]), "+f"(c[1]), "+f"(c[2]), "+f"(c[3])
        : "r"(a[0]), "r"(a[1]), "r"(a[2]), "r"(a[3]), "r"(b[0]), "r"(b[1]));
}

#define STAGE_B 20480
#define GSMEM   (4 * STAGE_B)

template <int MODE>
__global__ void __launch_bounds__(128, 2)
mma_gemm4(const bf16* __restrict__ A, const bf16* __restrict__ W, void* __restrict__ Cv,
          const float* __restrict__ hval, const float* __restrict__ rs, int rowBase) {
    extern __shared__ __align__(16) char dynsm[];
    int tid = threadIdx.x;
    int lane = tid & 31, wid = tid >> 5;
    int wm = wid >> 1, wn = wid & 1;
    int brow = rowBase + blockIdx.y * 128, bcol = blockIdx.x * 128;

    const bf16* aptr = A + (size_t)(brow + tid) * 512;
    const bf16* bptr = W + (size_t)(bcol + tid) * 512;
    char* aDst = dynsm + tid * 80;
    char* bDst = dynsm + 10240 + tid * 80;

    unsigned smBase = (unsigned)__cvta_generic_to_shared(dynsm);
    unsigned aOff = (unsigned)((wm * 64 + (lane & 15)) * 80 + ((lane >> 4) << 4));
    unsigned bOff = (unsigned)(10240 + (wn * 64 + ((lane >> 3) & 1) * 8 + (lane & 7)) * 80
                               + ((lane >> 4) << 4));

    float acc[4][8][4];
    #pragma unroll
    for (int i = 0; i < 4; i++)
        #pragma unroll
        for (int j = 0; j < 8; j++)
            #pragma unroll
            for (int e = 0; e < 4; e++) acc[i][j][e] = 0.f;

    #pragma unroll
    for (int s = 0; s < 3; s++) {
        char* ad = aDst + s * STAGE_B;
        char* bd = bDst + s * STAGE_B;
        const bf16* as = aptr + s * 32;
        const bf16* bs = bptr + s * 32;
        #pragma unroll
        for (int c = 0; c < 4; c++) { cp16(ad + c * 16, as + c * 8); cp16(bd + c * 16, bs + c * 8); }
        asm volatile("cp.async.commit_group;");
    }

    #pragma unroll 1
    for (int it = 0; it < 16; it++) {
        if (it < 14)      asm volatile("cp.async.wait_group 2;");
        else if (it == 14) asm volatile("cp.async.wait_group 1;");
        else               asm volatile("cp.async.wait_group 0;");
        __syncthreads();
        if (it + 3 < 16) {
            int s = it + 3;
            char* ad = aDst + (s & 3) * STAGE_B;
            char* bd = bDst + (s & 3) * STAGE_B;
            const bf16* as = aptr + s * 32;
            const bf16* bs = bptr + s * 32;
            #pragma unroll
            for (int c = 0; c < 4; c++) { cp16(ad + c * 16, as + c * 8); cp16(bd + c * 16, bs + c * 8); }
            asm volatile("cp.async.commit_group;");
        }
        unsigned base = smBase + (unsigned)((it & 3) * STAGE_B);
        #pragma unroll
        for (int ks = 0; ks < 2; ks++) {
            unsigned a[4][4], b[8][2];
            #pragma unroll
            for (int mi = 0; mi < 4; mi++)
                ldsm4(a[mi][0], a[mi][1], a[mi][2], a[mi][3],
                      base + aOff + mi * (16 * 80) + ks * 32);
            #pragma unroll
            for (int pr = 0; pr < 4; pr++)
                ldsm4(b[2*pr][0], b[2*pr+1][0], b[2*pr][1], b[2*pr+1][1],
                      base + bOff + pr * (16 * 80) + ks * 32);
            #pragma unroll
            for (int mi = 0; mi < 4; mi++)
                #pragma unroll
                for (int ni = 0; ni < 8; ni++)
                    mma16816(acc[mi][ni], a[mi], b[ni]);
        }
    }

    #pragma unroll
    for (int mi = 0; mi < 4; mi++) {
        int r0 = brow + wm * 64 + mi * 16 + (lane >> 2);
        #pragma unroll
        for (int half = 0; half < 2; half++) {
            int r = r0 + half * 8;
            float sc = 1.f;
            if (MODE == 1) {
                int nseg = (r / Tt) % Nn;
                sc = fminf(fmaxf(rs[nseg], 0.f), 1.f);
            }
            #pragma unroll
            for (int ni = 0; ni < 8; ni++) {
                int c = bcol + wn * 64 + ni * 8 + (lane & 3) * 2;
                float x = acc[mi][ni][half * 2 + 0];
                float y = acc[mi][ni][half * 2 + 1];
                if (MODE == 0) {
                    *(__nv_bfloat162*)((bf16*)Cv + (size_t)r * 512 + c) =
                        __floats2bfloat162_rn(x, y);
                } else {
                    const float2 hv = *(const float2*)(hval + (size_t)r * 512 + c);
                    float2 o; o.x = hv.x + x * sc; o.y = hv.y + y * sc;
                    *(float2*)((float*)Cv + (size_t)r * 512 + c) = o;
                }
            }
        }
    }
}

// ---------------- mixed: smem-tiled sparse mix (+ batch offset) ----------------
__global__ void __launch_bounds__(256)
mixed2(const bf16* __restrict__ v, bf16* __restrict__ mixed, int b0) {
    __shared__ bf16 sv[128][128];
    __shared__ unsigned char su[128][16];
    __shared__ float swt[128][16];
    int nt = blockIdx.x, h = blockIdx.y, b = b0 + blockIdx.z;
    int tid = threadIdx.x, lane = tid & 31, w = tid >> 5;

    {
        int j = tid >> 1, tt = tid & 1;
        const uint4* src = (const uint4*)(v + ((size_t)(b * 128 + j) * 64 + nt * 2 + tt) * 512
                                            + h * 64);
        uint4* dst = (uint4*)&sv[j][tt * 64];
        #pragma unroll
        for (int c = 0; c < 8; c++) dst[c] = src[c];
    }
    {
        int base = (b * 8 + h) * 128;
        #pragma unroll
        for (int e = tid * 8; e < tid * 8 + 8; e++) {
            int i = e >> 4, kk = e & 15;
            int j = g_idx[(size_t)(base + i) * 16 + kk];
            su[i][kk] = (unsigned char)j;
            swt[i][kk] = g_attn[(size_t)(base + i) * 128 + j];
        }
    }
    __syncthreads();

    int tt = lane >> 4;
    for (int r = 0; r < 16; r++) {
        int i = w * 16 + r;
        float a0 = 0.f, a1 = 0.f, a2 = 0.f, a3 = 0.f;
        #pragma unroll
        for (int kk = 0; kk < 16; kk++) {
            int j = su[i][kk];
            float wt = swt[i][kk];
            uint2 vv = *(const uint2*)&sv[j][lane * 4];
            float2 f0 = __bfloat1622float2(*(__nv_bfloat162*)&vv.x);
            float2 f1 = __bfloat1622float2(*(__nv_bfloat162*)&vv.y);
            a0 = fmaf(wt, f0.x, a0); a1 = fmaf(wt, f0.y, a1);
            a2 = fmaf(wt, f1.x, a2); a3 = fmaf(wt, f1.y, a3);
        }
        int d = (lane & 15) * 4;
        __nv_bfloat162 o0 = __floats2bfloat162_rn(a0, a1);
        __nv_bfloat162 o1 = __floats2bfloat162_rn(a2, a3);
        uint2 ov; ov.x = *(unsigned*)&o0; ov.y = *(unsigned*)&o1;
        *(uint2*)(mixed + ((size_t)(b * 128 + i) * 64 + nt * 2 + tt) * 512 + h * 64 + d) = ov;
    }
}

// ---------------- head means ----------------
__global__ void means_kernel(float* __restrict__ out_attn, float* __restrict__ out_raw) {
    int idx = blockIdx.x * 256 + threadIdx.x;
    if (idx >= Bb * Nn * Nn) return;
    int b = idx / (Nn * Nn);
    int rem = idx % (Nn * Nn);
    float sa = 0.f, sr = 0.f;
    #pragma unroll
    for (int h = 0; h < Hh; h++) {
        size_t p = ((size_t)(b * Hh + h)) * Nn * Nn + rem;
        sa += g_attn[p];
        sr += g_raw[p];
    }
    out_attn[idx] = sa * (1.0f / Hh);
    out_raw[idx]  = sr * (1.0f / Hh);
}

// ---------------- launch: R10 two-half pipeline + K-split qk ----------------
extern "C" void kernel_launch(void* const* d_in, const int* in_sizes, int n_in,
                              void* d_out, int out_size) {
    const float* h_val = (const float*)d_in[0];
    const float* h_map = (const float*)d_in[1];
    const float* adj   = (const float*)d_in[2];
    const float* q_w   = (const float*)d_in[3];
    const float* k_w   = (const float*)d_in[4];
    const float* v_w   = (const float*)d_in[5];
    const float* o_w   = (const float*)d_in[6];
    const float* rs    = (const float*)d_in[7];
    float* out = (float*)d_out;

    bf16 *hvb, *vwb, *owb, *v, *mixed;
    float *wtq, *wtk, *qkp;
    cudaGetSymbolAddress((void**)&hvb,   g_hvb);
    cudaGetSymbolAddress((void**)&vwb,   g_vwb);
    cudaGetSymbolAddress((void**)&owb,   g_owb);
    cudaGetSymbolAddress((void**)&wtq,   g_wtq);
    cudaGetSymbolAddress((void**)&wtk,   g_wtk);
    cudaGetSymbolAddress((void**)&qkp,   g_qkp);
    cudaGetSymbolAddress((void**)&v,     g_v);
    cudaGetSymbolAddress((void**)&mixed, g_mixed);

    static cudaStream_t s1 = nullptr, s2 = nullptr;
    static cudaEvent_t evF = nullptr, evW = nullptr, evScores = nullptr,
                       evS1 = nullptr, evB = nullptr;
    if (s1 == nullptr) {
        cudaStreamCreateWithFlags(&s1, cudaStreamNonBlocking);
        cudaStreamCreateWithFlags(&s2, cudaStreamNonBlocking);
        cudaEventCreateWithFlags(&evF,      cudaEventDisableTiming);
        cudaEventCreateWithFlags(&evW,      cudaEventDisableTiming);
        cudaEventCreateWithFlags(&evScores, cudaEventDisableTiming);
        cudaEventCreateWithFlags(&evS1,     cudaEventDisableTiming);
        cudaEventCreateWithFlags(&evB,      cudaEventDisableTiming);
        cudaFuncSetAttribute(mma_gemm4<0>, cudaFuncAttributeMaxDynamicSharedMemorySize, GSMEM);
        cudaFuncSetAttribute(mma_gemm4<1>, cudaFuncAttributeMaxDynamicSharedMemorySize, GSMEM);
    }

    cudaStream_t s0 = 0;
    const int N4H = ROWS_H * Dd / 4;

    // fork
    cudaEventRecord(evF, s0);
    cudaStreamWaitEvent(s1, evF, 0);
    cudaStreamWaitEvent(s2, evF, 0);

    // (1,2) s1: weight converts
    f2bf<<<(Dd*Dd/4 + 255)/256, 256, 0, s1>>>((const float4*)v_w, (uint2*)vwb, Dd*Dd/4);
    f2bf<<<(Dd*Dd/4 + 255)/256, 256, 0, s1>>>((const float4*)o_w, (uint2*)owb, Dd*Dd/4);
    cudaEventRecord(evW, s1);

    // (3,4) s0: half A convert + v-GEMM (index 4 -> profiled)
    f2bf<<<(N4H + 255)/256, 256, 0, s0>>>((const float4*)h_val, (uint2*)hvb, N4H);
    cudaStreamWaitEvent(s0, evW, 0);
    mma_gemm4<0><<<dim3(4, 256), 128, GSMEM, s0>>>(hvb, vwb, (void*)v, nullptr, nullptr, 0);

    // s1: scores chain with K-split qk (fp32) + means
    transpose512<<<dim3(16, 16), dim3(32, 8), 0, s1>>>(q_w, wtq);
    transpose512<<<dim3(16, 16), dim3(32, 8), 0, s1>>>(k_w, wtk);
    zmap_kernel<<<Bb * Nn, Dd, 0, s1>>>(h_map);
    qk_part<<<dim3(8, 8, 4), 256, 0, s1>>>(qkp);
    qk_reduce<<<1024, 256, 0, s1>>>(qkp);
    scores2<<<dim3(2, Hh, Bb), 256, 0, s1>>>(adj);
    cudaEventRecord(evScores, s1);
    means_kernel<<<(MEAN_ELEMS + 255)/256, 256, 0, s1>>>(out + OUT0_ELEMS,
                                                         out + OUT0_ELEMS + MEAN_ELEMS);
    cudaEventRecord(evS1, s1);

    // s2: half B convert (no weight dep) + v-GEMM
    f2bf<<<(N4H + 255)/256, 256, 0, s2>>>((const float4*)(h_val + (size_t)ROWS_H * Dd),
                                          (uint2*)(hvb + (size_t)ROWS_H * Dd), N4H);
    cudaStreamWaitEvent(s2, evW, 0);
    mma_gemm4<0><<<dim3(4, 256), 128, GSMEM, s2>>>(hvb, vwb, (void*)v, nullptr, nullptr,
                                                   ROWS_H);

    // s0 half A: mixed + o-GEMM
    cudaStreamWaitEvent(s0, evScores, 0);
    mixed2<<<dim3(32, Hh, 4), 256, 0, s0>>>(v, mixed, 0);
    mma_gemm4<1><<<dim3(4, 256), 128, GSMEM, s0>>>(mixed, owb, (void*)out, h_val, rs, 0);

    // s2 half B: mixed + o-GEMM
    cudaStreamWaitEvent(s2, evScores, 0);
    mixed2<<<dim3(32, Hh, 4), 256, 0, s2>>>(v, mixed, 4);
    mma_gemm4<1><<<dim3(4, 256), 128, GSMEM, s2>>>(mixed, owb, (void*)out, h_val, rs,
                                                   ROWS_H);
    cudaEventRecord(evB, s2);

    // final join
    cudaStreamWaitEvent(s0, evB, 0);
    cudaStreamWaitEvent(s0, evS1, 0);
}

// round 16
// speedup vs baseline: 1.0883x; 1.0095x over previous
#include <cuda_runtime.h>
#include <cuda_bf16.h>
#include <math.h>
#include <stdint.h>

#define Bb 8
#define Nn 128
#define Tt 64
#define Dd 512
#define Hh 8
#define HD 64
#define TOPK 16
#define SCALE 0.125f

#define OUT0_ELEMS (Bb*Nn*Tt*Dd)
#define MEAN_ELEMS (Bb*Nn*Nn)
#define ROWS_H     32768          // rows per half

typedef __nv_bfloat16 bf16;

// ---------------- static device scratch ----------------
__device__ float g_z[Bb*Nn*Dd];
__device__ float g_q[Bb*Nn*Dd];
__device__ float g_k[Bb*Nn*Dd];
__device__ float g_wtq[Dd*Dd];
__device__ float g_wtk[Dd*Dd];
__device__ float g_qkp[4*1024*1024];     // K-split partials
__device__ float g_attn[Bb*Hh*Nn*Nn];
__device__ float g_raw[Bb*Hh*Nn*Nn];
__device__ int   g_idx[Bb*Hh*Nn*TOPK];
__device__ bf16  g_hvb[Bb*Nn*Tt*Dd];
__device__ bf16  g_vwb[Dd*Dd];
__device__ bf16  g_owb[Dd*Dd];
__device__ bf16  g_v[Bb*Nn*Tt*Dd];
__device__ bf16  g_mixed[Bb*Nn*Tt*Dd];

// ---------------- fp32 -> bf16 (generic) ----------------
__global__ void f2bf(const float4* __restrict__ x, uint2* __restrict__ y, int n4) {
    int i = blockIdx.x * 256 + threadIdx.x;
    if (i >= n4) return;
    float4 f = x[i];
    __nv_bfloat162 a = __floats2bfloat162_rn(f.x, f.y);
    __nv_bfloat162 b = __floats2bfloat162_rn(f.z, f.w);
    uint2 u; u.x = *(unsigned*)&a; u.y = *(unsigned*)&b;
    y[i] = u;
}

// ---------------- both projection weights -> bf16 in ONE launch ----------------
__global__ void f2bf_weights(const float4* __restrict__ vw, const float4* __restrict__ ow) {
    int i = blockIdx.x * 256 + threadIdx.x;         // 0 .. 131071
    const int n4 = Dd * Dd / 4;                     // 65536 per weight
    const float4* src = (i < n4) ? vw : ow;
    uint2* dst = (i < n4) ? (uint2*)g_vwb : (uint2*)g_owb;
    int j = (i < n4) ? i : i - n4;
    float4 f = src[j];
    __nv_bfloat162 a = __floats2bfloat162_rn(f.x, f.y);
    __nv_bfloat162 b = __floats2bfloat162_rn(f.z, f.w);
    uint2 u; u.x = *(unsigned*)&a; u.y = *(unsigned*)&b;
    dst[j] = u;
}

// ---------------- weight transpose wt[k][n] = w[n][k] ----------------
__global__ void transpose512(const float* __restrict__ w, float* __restrict__ wt) {
    __shared__ float tile[32][33];
    int bx = blockIdx.x * 32, by = blockIdx.y * 32;
    int tx = threadIdx.x, ty = threadIdx.y;
    #pragma unroll
    for (int i = 0; i < 32; i += 8)
        tile[ty + i][tx] = w[(by + ty + i) * Dd + bx + tx];
    __syncthreads();
    #pragma unroll
    for (int i = 0; i < 32; i += 8)
        wt[(bx + ty + i) * Dd + by + tx] = tile[tx][ty + i];
}

// ---------------- z_map mean ----------------
__global__ void zmap_kernel(const float* __restrict__ hmap) {
    int bn = blockIdx.x;
    int d  = threadIdx.x;
    const float* p = hmap + (size_t)bn * Tt * Dd + d;
    float s = 0.f;
    #pragma unroll 8
    for (int t = 0; t < Tt; t++) s += p[t * Dd];
    g_z[bn * Dd + d] = s * (1.0f / Tt);
}

// ---------------- q/k projection: K-split partials (full wave), fp32 ----------------
__global__ void __launch_bounds__(256)
qk_part(float* __restrict__ part) {
    __shared__ float As[8][128];
    __shared__ float Bs[8][128];
    int bx = blockIdx.x, by = blockIdx.y, kc = blockIdx.z;
    const float* Bt = (bx < 4) ? g_wtq : g_wtk;
    int bcolL = (bx & 3) * 128;
    int brow = by * 128;
    int kbase = kc * 128;
    int tid = threadIdx.x;
    int tr = (tid / 16) * 8, tc = (tid % 16) * 8;
    int aRow = tid >> 1, aCol4 = (tid & 1) * 4;
    int bRow = tid >> 5, bCol4 = (tid & 31) * 4;

    float acc[8][8];
    #pragma unroll
    for (int i = 0; i < 8; i++)
        #pragma unroll
        for (int j = 0; j < 8; j++) acc[i][j] = 0.f;

    for (int k0 = 0; k0 < 128; k0 += 8) {
        float4 av = *(const float4*)(g_z + (size_t)(brow + aRow) * 512 + kbase + k0 + aCol4);
        As[aCol4 + 0][aRow] = av.x; As[aCol4 + 1][aRow] = av.y;
        As[aCol4 + 2][aRow] = av.z; As[aCol4 + 3][aRow] = av.w;
        *(float4*)&Bs[bRow][bCol4] =
            *(const float4*)(Bt + (size_t)(kbase + k0 + bRow) * 512 + bcolL + bCol4);
        __syncthreads();
        #pragma unroll
        for (int kk = 0; kk < 8; kk++) {
            float ar[8], br[8];
            *(float4*)&ar[0] = *(float4*)&As[kk][tr];
            *(float4*)&ar[4] = *(float4*)&As[kk][tr + 4];
            *(float4*)&br[0] = *(float4*)&Bs[kk][tc];
            *(float4*)&br[4] = *(float4*)&Bs[kk][tc + 4];
            #pragma unroll
            for (int i = 0; i < 8; i++)
                #pragma unroll
                for (int j = 0; j < 8; j++) acc[i][j] = fmaf(ar[i], br[j], acc[i][j]);
        }
        __syncthreads();
    }
    #pragma unroll
    for (int i = 0; i < 8; i++) {
        int r = brow + tr + i;
        #pragma unroll
        for (int g = 0; g < 2; g++) {
            int c = bx * 128 + tc + g * 4;
            float4 o;
            o.x = acc[i][g*4+0]; o.y = acc[i][g*4+1];
            o.z = acc[i][g*4+2]; o.w = acc[i][g*4+3];
            *(float4*)(part + ((size_t)kc * 1024 + r) * 1024 + c) = o;
        }
    }
}

__global__ void qk_reduce(const float* __restrict__ part) {
    int i4 = blockIdx.x * 256 + threadIdx.x;
    if (i4 >= 1024 * 256) return;
    int row = i4 >> 8, col = (i4 & 255) * 4;
    float4 s = *(const float4*)(part + (size_t)row * 1024 + col);
    #pragma unroll
    for (int kc = 1; kc < 4; kc++) {
        float4 p = *(const float4*)(part + ((size_t)kc * 1024 + row) * 1024 + col);
        s.x += p.x; s.y += p.y; s.z += p.z; s.w += p.w;
    }
    if (col < 512) *(float4*)(g_q + (size_t)row * 512 + col) = s;
    else           *(float4*)(g_k + (size_t)row * 512 + col - 512) = s;
}

// ---------------- scores (warp-per-row, REDUX topk) ----------------
__device__ __forceinline__ unsigned fenc(float v) {
    int b = __float_as_int(v);
    return (b >= 0) ? ((unsigned)b | 0x80000000u) : ~(unsigned)b;
}
__device__ __forceinline__ float wmax(float v) {
    #pragma unroll
    for (int o = 16; o; o >>= 1) v = fmaxf(v, __shfl_xor_sync(0xffffffffu, v, o));
    return v;
}
__device__ __forceinline__ float wsum(float v) {
    #pragma unroll
    for (int o = 16; o; o >>= 1) v += __shfl_xor_sync(0xffffffffu, v, o);
    return v;
}

__global__ void __launch_bounds__(256)
scores2(const float* __restrict__ adj) {
    __shared__ float ks[64][128];
    int ih = blockIdx.x, h = blockIdx.y, b = blockIdx.z;
    int tid = threadIdx.x, lane = tid & 31, w = tid >> 5;

    {
        int j = tid >> 1, dh = (tid & 1) * 32;
        const float* kp = g_k + (size_t)(b * 128 + j) * 512 + h * 64 + dh;
        #pragma unroll
        for (int f = 0; f < 8; f++) {
            float4 v = *(const float4*)(kp + f * 4);
            ks[dh + f*4 + 0][j] = v.x; ks[dh + f*4 + 1][j] = v.y;
            ks[dh + f*4 + 2][j] = v.z; ks[dh + f*4 + 3][j] = v.w;
        }
    }
    __syncthreads();

    for (int r = 0; r < 8; r++) {
        int i = ih * 64 + w * 8 + r;
        float2 qr = *(const float2*)(g_q + (size_t)(b * 128 + i) * 512 + h * 64 + lane * 2);
        float a0 = 0.f, a1 = 0.f, a2 = 0.f, a3 = 0.f;
        #pragma unroll
        for (int d = 0; d < 64; d++) {
            float qd = __shfl_sync(0xffffffffu, (d & 1) ? qr.y : qr.x, d >> 1);
            float4 kv = *(const float4*)&ks[d][lane * 4];
            a0 = fmaf(qd, kv.x, a0); a1 = fmaf(qd, kv.y, a1);
            a2 = fmaf(qd, kv.z, a2); a3 = fmaf(qd, kv.w, a3);
        }
        float4 adjv = *(const float4*)(adj + (size_t)(b * 128 + i) * 128 + lane * 4);
        float s4[4];
        s4[0] = a0 * SCALE + logf(fmaxf(adjv.x, 1e-12f));
        s4[1] = a1 * SCALE + logf(fmaxf(adjv.y, 1e-12f));
        s4[2] = a2 * SCALE + logf(fmaxf(adjv.z, 1e-12f));
        s4[3] = a3 * SCALE + logf(fmaxf(adjv.w, 1e-12f));

        float m = wmax(fmaxf(fmaxf(s4[0], s4[1]), fmaxf(s4[2], s4[3])));
        float e4[4];
        #pragma unroll
        for (int q = 0; q < 4; q++) e4[q] = expf(s4[q] - m);
        float sum1 = wsum(e4[0] + e4[1] + e4[2] + e4[3]);

        size_t rb = ((size_t)(b * 8 + h) * 128 + i) * 128;
        float4 rv; rv.x = e4[0]/sum1; rv.y = e4[1]/sum1; rv.z = e4[2]/sum1; rv.w = e4[3]/sum1;
        *(float4*)(g_raw + rb + lane * 4) = rv;

        unsigned u4[4];
        #pragma unroll
        for (int q = 0; q < 4; q++) u4[q] = fenc(s4[q]);
        int myj = 0;
        for (int itk = 0; itk < TOPK; itk++) {
            unsigned ub = u4[0]; int jb = lane * 4;
            #pragma unroll
            for (int q = 1; q < 4; q++)
                if (u4[q] > ub) { ub = u4[q]; jb = lane * 4 + q; }
            unsigned gm = __reduce_max_sync(0xffffffffu, ub);
            unsigned jm = (ub == gm) ? (unsigned)jb : 0xFFFFu;
            unsigned js = __reduce_min_sync(0xffffffffu, jm);
            if (lane == itk) myj = (int)js;
            if ((js >> 2) == (unsigned)lane) u4[js & 3] = 0u;
        }
        float es = 0.f;
        #pragma unroll
        for (int q = 0; q < 4; q++) if (u4[q] == 0u) es += e4[q];
        float sum2 = wsum(es);
        float4 av;
        av.x = (u4[0] == 0u) ? e4[0]/sum2 : 0.f;
        av.y = (u4[1] == 0u) ? e4[1]/sum2 : 0.f;
        av.z = (u4[2] == 0u) ? e4[2]/sum2 : 0.f;
        av.w = (u4[3] == 0u) ? e4[3]/sum2 : 0.f;
        *(float4*)(g_attn + rb + lane * 4) = av;
        if (lane < TOPK)
            g_idx[((size_t)(b * 8 + h) * 128 + i) * TOPK + lane] = myj;
    }
}

// ================== bf16 HMMA GEMM (R10 champion: BK=32, 4-stage) ==================
__device__ __forceinline__ void cp16(void* smem, const void* g) {
    unsigned s = (unsigned)__cvta_generic_to_shared(smem);
    asm volatile("cp.async.cg.shared.global [%0], [%1], 16;" :: "r"(s), "l"(g));
}
__device__ __forceinline__ void ldsm4(unsigned& r0, unsigned& r1, unsigned& r2, unsigned& r3,
                                      unsigned addr) {
    asm volatile("ldmatrix.sync.aligned.m8n8.x4.shared.b16 {%0,%1,%2,%3}, [%4];"
                 : "=r"(r0), "=r"(r1), "=r"(r2), "=r"(r3) : "r"(addr));
}
__device__ __forceinline__ void mma16816(float* c, const unsigned* a, const unsigned* b) {
    asm volatile(
        "mma.sync.aligned.m16n8k16.row.col.f32.bf16.bf16.f32 "
        "{%0,%1,%2,%3}, {%4,%5,%6,%7}, {%8,%9}, {%0,%1,%2,%3};"
        : "+f"(c[0]), "+f"(c[1]), "+f"(c[2]), "+f"(c[3])
        : "r"(a[0]), "r"(a[1]), "r"(a[2]), "r"(a[3]), "r"(b[0]), "r"(b[1]));
}

#define STAGE_B 20480
#define GSMEM   (4 * STAGE_B)

template <int MODE>
__global__ void __launch_bounds__(128, 2)
mma_gemm4(const bf16* __restrict__ A, const bf16* __restrict__ W, void* __restrict__ Cv,
          const float* __restrict__ hval, const float* __restrict__ rs, int rowBase) {
    extern __shared__ __align__(16) char dynsm[];
    int tid = threadIdx.x;
    int lane = tid & 31, wid = tid >> 5;
    int wm = wid >> 1, wn = wid & 1;
    int brow = rowBase + blockIdx.y * 128, bcol = blockIdx.x * 128;

    const bf16* aptr = A + (size_t)(brow + tid) * 512;
    const bf16* bptr = W + (size_t)(bcol + tid) * 512;
    char* aDst = dynsm + tid * 80;
    char* bDst = dynsm + 10240 + tid * 80;

    unsigned smBase = (unsigned)__cvta_generic_to_shared(dynsm);
    unsigned aOff = (unsigned)((wm * 64 + (lane & 15)) * 80 + ((lane >> 4) << 4));
    unsigned bOff = (unsigned)(10240 + (wn * 64 + ((lane >> 3) & 1) * 8 + (lane & 7)) * 80
                               + ((lane >> 4) << 4));

    float acc[4][8][4];
    #pragma unroll
    for (int i = 0; i < 4; i++)
        #pragma unroll
        for (int j = 0; j < 8; j++)
            #pragma unroll
            for (int e = 0; e < 4; e++) acc[i][j][e] = 0.f;

    #pragma unroll
    for (int s = 0; s < 3; s++) {
        char* ad = aDst + s * STAGE_B;
        char* bd = bDst + s * STAGE_B;
        const bf16* as = aptr + s * 32;
        const bf16* bs = bptr + s * 32;
        #pragma unroll
        for (int c = 0; c < 4; c++) { cp16(ad + c * 16, as + c * 8); cp16(bd + c * 16, bs + c * 8); }
        asm volatile("cp.async.commit_group;");
    }

    #pragma unroll 1
    for (int it = 0; it < 16; it++) {
        if (it < 14)      asm volatile("cp.async.wait_group 2;");
        else if (it == 14) asm volatile("cp.async.wait_group 1;");
        else               asm volatile("cp.async.wait_group 0;");
        __syncthreads();
        if (it + 3 < 16) {
            int s = it + 3;
            char* ad = aDst + (s & 3) * STAGE_B;
            char* bd = bDst + (s & 3) * STAGE_B;
            const bf16* as = aptr + s * 32;
            const bf16* bs = bptr + s * 32;
            #pragma unroll
            for (int c = 0; c < 4; c++) { cp16(ad + c * 16, as + c * 8); cp16(bd + c * 16, bs + c * 8); }
            asm volatile("cp.async.commit_group;");
        }
        unsigned base = smBase + (unsigned)((it & 3) * STAGE_B);
        #pragma unroll
        for (int ks = 0; ks < 2; ks++) {
            unsigned a[4][4], b[8][2];
            #pragma unroll
            for (int mi = 0; mi < 4; mi++)
                ldsm4(a[mi][0], a[mi][1], a[mi][2], a[mi][3],
                      base + aOff + mi * (16 * 80) + ks * 32);
            #pragma unroll
            for (int pr = 0; pr < 4; pr++)
                ldsm4(b[2*pr][0], b[2*pr+1][0], b[2*pr][1], b[2*pr+1][1],
                      base + bOff + pr * (16 * 80) + ks * 32);
            #pragma unroll
            for (int mi = 0; mi < 4; mi++)
                #pragma unroll
                for (int ni = 0; ni < 8; ni++)
                    mma16816(acc[mi][ni], a[mi], b[ni]);
        }
    }

    #pragma unroll
    for (int mi = 0; mi < 4; mi++) {
        int r0 = brow + wm * 64 + mi * 16 + (lane >> 2);
        #pragma unroll
        for (int half = 0; half < 2; half++) {
            int r = r0 + half * 8;
            float sc = 1.f;
            if (MODE == 1) {
                int nseg = (r / Tt) % Nn;
                sc = fminf(fmaxf(rs[nseg], 0.f), 1.f);
            }
            #pragma unroll
            for (int ni = 0; ni < 8; ni++) {
                int c = bcol + wn * 64 + ni * 8 + (lane & 3) * 2;
                float x = acc[mi][ni][half * 2 + 0];
                float y = acc[mi][ni][half * 2 + 1];
                if (MODE == 0) {
                    *(__nv_bfloat162*)((bf16*)Cv + (size_t)r * 512 + c) =
                        __floats2bfloat162_rn(x, y);
                } else {
                    const float2 hv = *(const float2*)(hval + (size_t)r * 512 + c);
                    float2 o; o.x = hv.x + x * sc; o.y = hv.y + y * sc;
                    *(float2*)((float*)Cv + (size_t)r * 512 + c) = o;
                }
            }
        }
    }
}

// ---------------- mixed: smem-tiled sparse mix (+ batch offset) ----------------
__global__ void __launch_bounds__(256)
mixed2(const bf16* __restrict__ v, bf16* __restrict__ mixed, int b0) {
    __shared__ bf16 sv[128][128];
    __shared__ unsigned char su[128][16];
    __shared__ float swt[128][16];
    int nt = blockIdx.x, h = blockIdx.y, b = b0 + blockIdx.z;
    int tid = threadIdx.x, lane = tid & 31, w = tid >> 5;

    {
        int j = tid >> 1, tt = tid & 1;
        const uint4* src = (const uint4*)(v + ((size_t)(b * 128 + j) * 64 + nt * 2 + tt) * 512
                                            + h * 64);
        uint4* dst = (uint4*)&sv[j][tt * 64];
        #pragma unroll
        for (int c = 0; c < 8; c++) dst[c] = src[c];
    }
    {
        int base = (b * 8 + h) * 128;
        #pragma unroll
        for (int e = tid * 8; e < tid * 8 + 8; e++) {
            int i = e >> 4, kk = e & 15;
            int j = g_idx[(size_t)(base + i) * 16 + kk];
            su[i][kk] = (unsigned char)j;
            swt[i][kk] = g_attn[(size_t)(base + i) * 128 + j];
        }
    }
    __syncthreads();

    int tt = lane >> 4;
    for (int r = 0; r < 16; r++) {
        int i = w * 16 + r;
        float a0 = 0.f, a1 = 0.f, a2 = 0.f, a3 = 0.f;
        #pragma unroll
        for (int kk = 0; kk < 16; kk++) {
            int j = su[i][kk];
            float wt = swt[i][kk];
            uint2 vv = *(const uint2*)&sv[j][lane * 4];
            float2 f0 = __bfloat1622float2(*(__nv_bfloat162*)&vv.x);
            float2 f1 = __bfloat1622float2(*(__nv_bfloat162*)&vv.y);
            a0 = fmaf(wt, f0.x, a0); a1 = fmaf(wt, f0.y, a1);
            a2 = fmaf(wt, f1.x, a2); a3 = fmaf(wt, f1.y, a3);
        }
        int d = (lane & 15) * 4;
        __nv_bfloat162 o0 = __floats2bfloat162_rn(a0, a1);
        __nv_bfloat162 o1 = __floats2bfloat162_rn(a2, a3);
        uint2 ov; ov.x = *(unsigned*)&o0; ov.y = *(unsigned*)&o1;
        *(uint2*)(mixed + ((size_t)(b * 128 + i) * 64 + nt * 2 + tt) * 512 + h * 64 + d) = ov;
    }
}

// ---------------- head means ----------------
__global__ void means_kernel(float* __restrict__ out_attn, float* __restrict__ out_raw) {
    int idx = blockIdx.x * 256 + threadIdx.x;
    if (idx >= Bb * Nn * Nn) return;
    int b = idx / (Nn * Nn);
    int rem = idx % (Nn * Nn);
    float sa = 0.f, sr = 0.f;
    #pragma unroll
    for (int h = 0; h < Hh; h++) {
        size_t p = ((size_t)(b * Hh + h)) * Nn * Nn + rem;
        sa += g_attn[p];
        sr += g_raw[p];
    }
    out_attn[idx] = sa * (1.0f / Hh);
    out_raw[idx]  = sr * (1.0f / Hh);
}

// ---------------- launch: R15 schedule, consolidated weight convert ----------------
extern "C" void kernel_launch(void* const* d_in, const int* in_sizes, int n_in,
                              void* d_out, int out_size) {
    const float* h_val = (const float*)d_in[0];
    const float* h_map = (const float*)d_in[1];
    const float* adj   = (const float*)d_in[2];
    const float* q_w   = (const float*)d_in[3];
    const float* k_w   = (const float*)d_in[4];
    const float* v_w   = (const float*)d_in[5];
    const float* o_w   = (const float*)d_in[6];
    const float* rs    = (const float*)d_in[7];
    float* out = (float*)d_out;

    bf16 *hvb, *vwb, *owb, *v, *mixed;
    float *wtq, *wtk, *qkp;
    cudaGetSymbolAddress((void**)&hvb,   g_hvb);
    cudaGetSymbolAddress((void**)&vwb,   g_vwb);
    cudaGetSymbolAddress((void**)&owb,   g_owb);
    cudaGetSymbolAddress((void**)&wtq,   g_wtq);
    cudaGetSymbolAddress((void**)&wtk,   g_wtk);
    cudaGetSymbolAddress((void**)&qkp,   g_qkp);
    cudaGetSymbolAddress((void**)&v,     g_v);
    cudaGetSymbolAddress((void**)&mixed, g_mixed);

    static cudaStream_t s1 = nullptr, s2 = nullptr;
    static cudaEvent_t evF = nullptr, evW = nullptr, evScores = nullptr,
                       evS1 = nullptr, evB = nullptr;
    if (s1 == nullptr) {
        cudaStreamCreateWithFlags(&s1, cudaStreamNonBlocking);
        cudaStreamCreateWithFlags(&s2, cudaStreamNonBlocking);
        cudaEventCreateWithFlags(&evF,      cudaEventDisableTiming);
        cudaEventCreateWithFlags(&evW,      cudaEventDisableTiming);
        cudaEventCreateWithFlags(&evScores, cudaEventDisableTiming);
        cudaEventCreateWithFlags(&evS1,     cudaEventDisableTiming);
        cudaEventCreateWithFlags(&evB,      cudaEventDisableTiming);
        cudaFuncSetAttribute(mma_gemm4<0>, cudaFuncAttributeMaxDynamicSharedMemorySize, GSMEM);
        cudaFuncSetAttribute(mma_gemm4<1>, cudaFuncAttributeMaxDynamicSharedMemorySize, GSMEM);
    }

    cudaStream_t s0 = 0;
    const int N4H = ROWS_H * Dd / 4;

    // fork
    cudaEventRecord(evF, s0);
    cudaStreamWaitEvent(s1, evF, 0);
    cudaStreamWaitEvent(s2, evF, 0);

    // (1) s1: both weights in one convert launch
    f2bf_weights<<<512, 256, 0, s1>>>((const float4*)v_w, (const float4*)o_w);
    cudaEventRecord(evW, s1);

    // s0: half A convert + v-GEMM
    f2bf<<<(N4H + 255)/256, 256, 0, s0>>>((const float4*)h_val, (uint2*)hvb, N4H);
    cudaStreamWaitEvent(s0, evW, 0);
    mma_gemm4<0><<<dim3(4, 256), 128, GSMEM, s0>>>(hvb, vwb, (void*)v, nullptr, nullptr, 0);

    // s1: scores chain with K-split qk (fp32) + means
    transpose512<<<dim3(16, 16), dim3(32, 8), 0, s1>>>(q_w, wtq);
    transpose512<<<dim3(16, 16), dim3(32, 8), 0, s1>>>(k_w, wtk);
    zmap_kernel<<<Bb * Nn, Dd, 0, s1>>>(h_map);
    qk_part<<<dim3(8, 8, 4), 256, 0, s1>>>(qkp);
    qk_reduce<<<1024, 256, 0, s1>>>(qkp);
    scores2<<<dim3(2, Hh, Bb), 256, 0, s1>>>(adj);
    cudaEventRecord(evScores, s1);
    means_kernel<<<(MEAN_ELEMS + 255)/256, 256, 0, s1>>>(out + OUT0_ELEMS,
                                                         out + OUT0_ELEMS + MEAN_ELEMS);
    cudaEventRecord(evS1, s1);

    // s2: half B convert (no weight dep) + v-GEMM
    f2bf<<<(N4H + 255)/256, 256, 0, s2>>>((const float4*)(h_val + (size_t)ROWS_H * Dd),
                                          (uint2*)(hvb + (size_t)ROWS_H * Dd), N4H);
    cudaStreamWaitEvent(s2, evW, 0);
    mma_gemm4<0><<<dim3(4, 256), 128, GSMEM, s2>>>(hvb, vwb, (void*)v, nullptr, nullptr,
                                                   ROWS_H);

    // s0 half A: mixed + o-GEMM
    cudaStreamWaitEvent(s0, evScores, 0);
    mixed2<<<dim3(32, Hh, 4), 256, 0, s0>>>(v, mixed, 0);
    mma_gemm4<1><<<dim3(4, 256), 128, GSMEM, s0>>>(mixed, owb, (void*)out, h_val, rs, 0);

    // s2 half B: mixed + o-GEMM
    cudaStreamWaitEvent(s2, evScores, 0);
    mixed2<<<dim3(32, Hh, 4), 256, 0, s2>>>(v, mixed, 4);
    mma_gemm4<1><<<dim3(4, 256), 128, GSMEM, s2>>>(mixed, owb, (void*)out, h_val, rs,
                                                   ROWS_H);
    cudaEventRecord(evB, s2);

    // final join
    cudaStreamWaitEvent(s0, evB, 0);
    cudaStreamWaitEvent(s0, evS1, 0);
}